// round 2
// baseline (speedup 1.0000x reference)
#include <cuda_runtime.h>
#include <cstdint>

#define NGRID 16384
#define NH    8192      // half-size complex FFT
#define LOG2NH 13
#define MODES 2049
#define BB    16
#define CIN   64
#define COUT  64
#define TDIM  256

// ---------------- scratch (static device globals; no allocation) -------------
__device__ float2 g_xft[(size_t)BB * MODES * CIN];   // (B, M, Cin)
__device__ float2 g_oft[(size_t)BB * COUT * MODES];  // (B, Cout, M)
__device__ float2 g_tmod[(size_t)BB * MODES];        // (B, M)

// ---------------- complex helpers -------------------------------------------
__device__ __forceinline__ float2 cmul(float2 a, float2 b) {
    return make_float2(a.x * b.x - a.y * b.y, a.x * b.y + a.y * b.x);
}
__device__ __forceinline__ float2 cadd(float2 a, float2 b) { return make_float2(a.x + b.x, a.y + b.y); }
__device__ __forceinline__ float2 csub(float2 a, float2 b) { return make_float2(a.x - b.x, a.y - b.y); }

// ---------------- in-smem forward DFT, length 8192 ---------------------------
// Input must be pre-stored in bit-reversed order; output natural order.
// TW[t] = exp(-2*pi*i*t/8192), t in [0, 4096).
__device__ void fft8192(float2* S, const float2* TW, int tid, int nthreads) {
    // radix-2 stage (len = 2), twiddle = 1
    for (int bf = tid; bf < NH / 2; bf += nthreads) {
        float2 u = S[2 * bf], v = S[2 * bf + 1];
        S[2 * bf]     = cadd(u, v);
        S[2 * bf + 1] = csub(u, v);
    }
    __syncthreads();
    // 6 combined radix-4 passes: la = 4,16,64,256,1024,4096
#pragma unroll
    for (int ls = 2; ls <= 12; ls += 2) {
        const int la    = 1 << ls;
        const int halfA = la >> 1;
        for (int q = tid; q < NH / 4; q += nthreads) {
            int j  = q & (halfA - 1);
            int g  = q >> (ls - 1);
            int p0 = (g << (ls + 1)) + j;
            float2 x0 = S[p0];
            float2 x1 = S[p0 + halfA];
            float2 x2 = S[p0 + la];
            float2 x3 = S[p0 + la + halfA];
            float2 wA = TW[j << (LOG2NH - ls)];
            float2 wB = TW[j << (LOG2NH - ls - 1)];
            float2 t1 = cmul(wA, x1);
            float2 t3 = cmul(wA, x3);
            float2 u0 = cadd(x0, t1), u1 = csub(x0, t1);
            float2 u2 = cadd(x2, t3), u3 = csub(x2, t3);
            float2 s2 = cmul(wB, u2);
            float2 s3 = cmul(wB, u3);
            float2 s3m = make_float2(s3.y, -s3.x);   // -i * s3
            S[p0]              = cadd(u0, s2);
            S[p0 + la]         = csub(u0, s2);
            S[p0 + halfA]      = cadd(u1, s3m);
            S[p0 + la + halfA] = csub(u1, s3m);
        }
        __syncthreads();
    }
}

// TW[t] = exp(-i*pi*t/4096); argument t/4096 is exactly representable.
__device__ __forceinline__ void build_twiddles(float2* TW, int tid, int nthreads) {
    for (int t = tid; t < NH / 2; t += nthreads) {
        float s, co;
        sincospif((float)t * (-1.0f / 4096.0f), &s, &co);
        TW[t] = make_float2(co, s);
    }
}

// ---------------- kernel 1: t_mod = t_emb @ dense^T (complex) ----------------
__global__ void tmod_kernel(const float* __restrict__ te,
                            const float* __restrict__ dr,
                            const float* __restrict__ di) {
    int idx = blockIdx.x * blockDim.x + threadIdx.x;
    if (idx >= BB * MODES) return;
    int b = idx & (BB - 1);
    int i = idx >> 4;
    const float* t  = te + b * TDIM;
    const float* rr = dr + (size_t)i * TDIM;
    const float* ri = di + (size_t)i * TDIM;
    float ar = 0.f, ai = 0.f;
#pragma unroll 8
    for (int k = 0; k < TDIM; ++k) {
        float tv = t[k];
        ar += tv * rr[k];
        ai += tv * ri[k];
    }
    g_tmod[(size_t)b * MODES + i] = make_float2(ar, ai);
}

// ---------------- kernel 2: forward rfft per (b, cin) ------------------------
__global__ void fwd_fft_kernel(const float* __restrict__ x) {
    extern __shared__ float2 sh[];
    float2* S  = sh;          // 8192 float2
    float2* TW = sh + NH;     // 4096 float2
    const int tid = threadIdx.x;
    const int nth = blockDim.x;
    const int b = blockIdx.x >> 6;
    const int c = blockIdx.x & 63;
    const float* xb = x + (size_t)b * NGRID * CIN + c;

    build_twiddles(TW, tid, nth);
    // pack z[m] = x[2m] + i x[2m+1] into bit-reversed positions
    for (int m = tid; m < NH; m += nth) {
        float re = xb[(size_t)(2 * m) * CIN];
        float im = xb[(size_t)(2 * m + 1) * CIN];
        int r = __brev((unsigned)m) >> (32 - LOG2NH);
        S[r] = make_float2(re, im);
    }
    __syncthreads();
    fft8192(S, TW, tid, nth);

    // real-FFT untangle for k = 0..2048, forward norm (1/N)
    const float invN = 1.0f / 16384.0f;
    for (int k = tid; k < MODES; k += nth) {
        float2 Zk = S[k];
        float2 Zc = S[(NH - k) & (NH - 1)];
        float2 Zcc = make_float2(Zc.x, -Zc.y);
        float2 E  = make_float2(0.5f * (Zk.x + Zcc.x), 0.5f * (Zk.y + Zcc.y));
        float2 Od = csub(Zk, Zcc);
        float2 O  = make_float2(0.5f * Od.y, -0.5f * Od.x);   // -i/2 * Od
        float s, co;
        sincospif((float)k * (-1.0f / 8192.0f), &s, &co);     // exp(-2*pi*i*k/16384)
        float2 w = make_float2(co, s);
        float2 X = cadd(E, cmul(w, O));
        g_xft[((size_t)b * MODES + k) * CIN + c] = make_float2(X.x * invN, X.y * invN);
    }
}

// ---------------- kernel 3: per-mode complex matmul + modulation -------------
// out_ft[b,i,o] = t_mod[b,i] * sum_c x_ft[b,i,c] * W[i,c,o]
__global__ __launch_bounds__(256) void specmul_kernel(const float* __restrict__ wr,
                                                      const float* __restrict__ wi) {
    __shared__ float  sWr[CIN * COUT];
    __shared__ float  sWi[CIN * COUT];
    __shared__ float2 sx[BB * CIN];
    __shared__ float2 stm[BB];
    const int i   = blockIdx.x;
    const int tid = threadIdx.x;

    const float* wrb = wr + (size_t)i * CIN * COUT;
    const float* wib = wi + (size_t)i * CIN * COUT;
    for (int t = tid; t < CIN * COUT; t += 256) {
        sWr[t] = wrb[t];
        sWi[t] = wib[t];
    }
    for (int t = tid; t < BB * CIN; t += 256) {
        int b = t >> 6, c = t & 63;
        sx[t] = g_xft[((size_t)b * MODES + i) * CIN + c];
    }
    if (tid < BB) stm[tid] = g_tmod[(size_t)tid * MODES + i];
    __syncthreads();

    const int o  = tid & 63;
    const int b0 = tid >> 6;     // 0..3
    float2 acc[4];
#pragma unroll
    for (int bb = 0; bb < 4; ++bb) acc[bb] = make_float2(0.f, 0.f);

#pragma unroll 4
    for (int c = 0; c < CIN; ++c) {
        float Wr = sWr[c * COUT + o];
        float Wi = sWi[c * COUT + o];
#pragma unroll
        for (int bb = 0; bb < 4; ++bb) {
            float2 xv = sx[(bb * 4 + b0) * CIN + c];
            acc[bb].x += xv.x * Wr - xv.y * Wi;
            acc[bb].y += xv.x * Wi + xv.y * Wr;
        }
    }
#pragma unroll
    for (int bb = 0; bb < 4; ++bb) {
        int b = bb * 4 + b0;
        float2 r = cmul(stm[b], acc[bb]);
        g_oft[((size_t)b * COUT + o) * MODES + i] = r;
    }
}

// ---------------- kernel 4: zero-padded irfft per (b, cout) ------------------
__global__ void inv_fft_kernel(float* __restrict__ out) {
    extern __shared__ float2 sh[];
    float2* S  = sh;
    float2* TW = sh + NH;
    const int tid = threadIdx.x;
    const int nth = blockDim.x;
    const int b = blockIdx.x >> 6;
    const int o = blockIdx.x & 63;
    const float2* of = g_oft + ((size_t)b * COUT + o) * MODES;

    build_twiddles(TW, tid, nth);

    // Build conj(Z)[k] (so forward DFT machinery computes the inverse),
    // store directly in bit-reversed order.
    for (int k = tid; k < NH; k += nth) {
        float2 OF = make_float2(0.f, 0.f);
        float2 OC = make_float2(0.f, 0.f);
        if (k < MODES) OF = of[k];
        if (k == 0) OF.y = 0.f;   // irfft semantics: bin 0 imaginary part is discarded
        if (k >= NH - 2048) {     // 8192-k <= 2048 (k>0 here)
            float2 t = of[NH - k];
            OC = make_float2(t.x, -t.y);
        }
        float2 A  = cadd(OF, OC);
        float2 Bd = csub(OF, OC);
        float s, co;
        sincospif((float)k * (1.0f / 8192.0f), &s, &co);   // exp(+2*pi*i*k/16384)
        float2 Bt = cmul(make_float2(co, s), Bd);
        // Z = A + i*Bt ; store conj(Z)
        float2 Zc = make_float2(A.x - Bt.y, -(A.y + Bt.x));
        S[__brev((unsigned)k) >> (32 - LOG2NH)] = Zc;
    }
    __syncthreads();
    fft8192(S, TW, tid, nth);

    // z[m] = conj(F[m]) -> out[2m] = F.x, out[2m+1] = -F.y
    float* ob = out + (size_t)b * NGRID * COUT + o;
    for (int m = tid; m < NH; m += nth) {
        float2 F = S[m];
        ob[(size_t)(2 * m) * COUT]     = F.x;
        ob[(size_t)(2 * m + 1) * COUT] = -F.y;
    }
}

// ---------------- launch ------------------------------------------------------
extern "C" void kernel_launch(void* const* d_in, const int* in_sizes, int n_in,
                              void* d_out, int out_size) {
    const float* x   = (const float*)d_in[0];
    const float* te  = (const float*)d_in[1];
    const float* wr  = (const float*)d_in[2];
    const float* wi  = (const float*)d_in[3];
    const float* drw = (const float*)d_in[4];
    const float* diw = (const float*)d_in[5];
    float* out = (float*)d_out;

    const int smem = (NH + NH / 2) * sizeof(float2);   // 98304 bytes
    cudaFuncSetAttribute(fwd_fft_kernel, cudaFuncAttributeMaxDynamicSharedMemorySize, smem);
    cudaFuncSetAttribute(inv_fft_kernel, cudaFuncAttributeMaxDynamicSharedMemorySize, smem);

    {
        int total = BB * MODES;
        int threads = 256;
        int blocks = (total + threads - 1) / threads;
        tmod_kernel<<<blocks, threads>>>(te, drw, diw);
    }
    fwd_fft_kernel<<<BB * CIN, 512, smem>>>(x);
    specmul_kernel<<<MODES, 256>>>(wr, wi);
    inv_fft_kernel<<<BB * COUT, 512, smem>>>(out);
}

// round 4
// speedup vs baseline: 1.3629x; 1.3629x over previous
#include <cuda_runtime.h>
#include <cstdint>

#define NGRID 16384
#define NH    8192
#define MODES 2049
#define BB    16
#define CIN   64
#define COUT  64
#define TDIM  256

#define ROW   546              // padded row stride (float2) for the 16 k1-rows
#define USIZE (16 * ROW)       // 8736 float2
#define TSIZE 4096             // twiddle table entries

// ---------------- scratch (static device globals; no allocation) -------------
__device__ float2 g_xft[(size_t)BB * MODES * CIN];   // (B, M, Cin)
__device__ float2 g_oft[(size_t)BB * COUT * MODES];  // (B, Cout, M)
__device__ float2 g_tmod[(size_t)BB * MODES];        // (B, M)

// ---------------- complex helpers -------------------------------------------
__device__ __forceinline__ float2 cmul(float2 a, float2 b) {
    return make_float2(a.x * b.x - a.y * b.y, a.x * b.y + a.y * b.x);
}
__device__ __forceinline__ float2 cadd(float2 a, float2 b) { return make_float2(a.x + b.x, a.y + b.y); }
__device__ __forceinline__ float2 csub(float2 a, float2 b) { return make_float2(a.x - b.x, a.y - b.y); }

// ---------------- register DFT-4 / DFT-16 ------------------------------------
__device__ __forceinline__ void dft4(float2& a, float2& b, float2& c, float2& d) {
    float2 t0 = cadd(a, c), t1 = csub(a, c), t2 = cadd(b, d), t3 = csub(b, d);
    a = cadd(t0, t2);
    c = csub(t0, t2);
    b = cadd(t1, make_float2(t3.y, -t3.x));   // t1 - i*t3
    d = cadd(t1, make_float2(-t3.y, t3.x));   // t1 + i*t3
}

// In: v[j] natural order. Out: X[k1 + 4*k2] stored in slot (4*k1 + k2).
#define SLOT(k) ((((k) & 3) << 2) | ((k) >> 2))
__device__ __forceinline__ void dft16(float2 v[16]) {
    const float C1 = 0.9238795325112867f, S1 = 0.3826834323650898f, R = 0.7071067811865476f;
#pragma unroll
    for (int j2 = 0; j2 < 4; ++j2)
        dft4(v[j2], v[4 + j2], v[8 + j2], v[12 + j2]);
    v[5]  = cmul(v[5],  make_float2( C1, -S1));   // W16^1
    v[6]  = cmul(v[6],  make_float2( R,  -R ));   // W16^2
    v[7]  = cmul(v[7],  make_float2( S1, -C1));   // W16^3
    v[9]  = cmul(v[9],  make_float2( R,  -R ));   // W16^2
    v[10] = make_float2(v[10].y, -v[10].x);       // W16^4 = -i
    v[11] = cmul(v[11], make_float2(-R,  -R ));   // W16^6
    v[13] = cmul(v[13], make_float2( S1, -C1));   // W16^3
    v[14] = cmul(v[14], make_float2(-R,  -R ));   // W16^6
    v[15] = cmul(v[15], make_float2(-C1,  S1));   // W16^9
#pragma unroll
    for (int k1 = 0; k1 < 4; ++k1)
        dft4(v[4 * k1], v[4 * k1 + 1], v[4 * k1 + 2], v[4 * k1 + 3]);
}

// ---------------- shared 8192-pt forward-DFT core ----------------------------
// On entry: v[a] = z[512*a + m] (natural), m = tid. T[t] = W_8192^t, t<4096.
// On exit:  v[SLOT(p)] = X[k1 + 16*q1 + 256*h + 512*p] for this thread's
//           (k1 = tid>>5, q1 = (tid>>1)&15, h = tid&1).
// If store_back: also stores X[k] to U[k + (k>>4)] (caller must sync before use).
__device__ __forceinline__ void fft8192_core(float2 v[16], float2* U,
                                             const float2* T, int tid,
                                             bool store_back) {
    const int m = tid;
    // ---- stage 1: DFT16 over a, twiddle W^{m*k}, store rows U[k*ROW + m]
    dft16(v);
    {
        float2 w = T[m];                 // W^m  (m < 512)
        float2 vw = make_float2(1.f, 0.f);
#pragma unroll
        for (int k = 0; k < 16; ++k) {
            U[k * ROW + m] = cmul(v[SLOT(k)], vw);
            vw = cmul(vw, w);
        }
    }
    __syncthreads();
    // ---- stage 2: per (k1,u): DFT16 over b, twiddle W_512^{u*q1}
    {
        const int k1 = tid >> 5, u = tid & 31;
        float2* Urow = U + k1 * ROW;
#pragma unroll
        for (int b = 0; b < 16; ++b) v[b] = Urow[32 * b + u];
        dft16(v);
        float2 w = T[16 * u];            // W_512^u
        float2 vw = make_float2(1.f, 0.f);
#pragma unroll
        for (int q1 = 0; q1 < 16; ++q1) {
            Urow[34 * q1 + u] = cmul(v[SLOT(q1)], vw);
            vw = cmul(vw, w);
        }
    }
    __syncthreads();
    // ---- stage 3: per (k1,q1,h): radix-2 combine + DFT16 over u'
    {
        const int k1 = tid >> 5, q1 = (tid >> 1) & 15, h = tid & 1;
        const float2* Urow = U + k1 * ROW + 34 * q1;
#pragma unroll
        for (int up = 0; up < 16; ++up) {
            float2 ca = Urow[up];
            float2 cb = Urow[up + 16];
            if (h == 0) v[up] = cadd(ca, cb);
            else        v[up] = cmul(csub(ca, cb), T[256 * up]);   // * W_32^{u'}
        }
        __syncthreads();                 // everyone done reading U
        dft16(v);
        if (store_back) {
            const int kb = k1 + 16 * q1 + 256 * h;
#pragma unroll
            for (int p = 0; p < 16; ++p) {
                int k = kb + 512 * p;
                U[k + (k >> 4)] = v[SLOT(p)];
            }
            __syncthreads();
        }
    }
}

__device__ __forceinline__ void build_table(float2* T, int tid) {
#pragma unroll
    for (int j = 0; j < TSIZE / 512; ++j) {
        int t = tid + 512 * j;
        float s, c;
        sincospif((float)t * (-1.0f / 4096.0f), &s, &c);   // W_8192^t
        T[t] = make_float2(c, s);
    }
}

// ---------------- kernel 1: t_mod = t_emb @ dense^T (complex) ----------------
__global__ void tmod_kernel(const float* __restrict__ te,
                            const float* __restrict__ dr,
                            const float* __restrict__ di) {
    int idx = blockIdx.x * blockDim.x + threadIdx.x;
    if (idx >= BB * MODES) return;
    int b = idx & (BB - 1);
    int i = idx >> 4;
    const float* t  = te + b * TDIM;
    const float* rr = dr + (size_t)i * TDIM;
    const float* ri = di + (size_t)i * TDIM;
    float ar = 0.f, ai = 0.f;
#pragma unroll 8
    for (int k = 0; k < TDIM; ++k) {
        float tv = t[k];
        ar += tv * rr[k];
        ai += tv * ri[k];
    }
    g_tmod[(size_t)b * MODES + i] = make_float2(ar, ai);
}

// ---------------- kernel 2: forward rfft per (b, cin) ------------------------
__global__ __launch_bounds__(512, 2) void fwd_fft_kernel(const float* __restrict__ x) {
    extern __shared__ float2 sh[];
    float2* U = sh;
    float2* T = sh + USIZE;
    const int tid = threadIdx.x;
    const int b = blockIdx.x >> 6;
    const int c = blockIdx.x & 63;
    const float* xb = x + (size_t)b * NGRID * CIN + c;

    // load z[512a + m] = x[1024a + 2m] + i x[1024a + 2m + 1]
    float2 v[16];
#pragma unroll
    for (int a = 0; a < 16; ++a) {
        size_t g = ((size_t)(1024 * a + 2 * tid)) * CIN;
        v[a] = make_float2(xb[g], xb[g + (size_t)CIN]);
    }
    build_table(T, tid);
    __syncthreads();

    fft8192_core(v, U, T, tid, true);

    // real-FFT untangle, forward norm (1/N)
    const float invN = 1.0f / 16384.0f;
    const float2 EJ[5] = {
        {1.f, 0.f},
        {0.98078528040323f, -0.19509032201613f},
        {0.92387953251129f, -0.38268343236509f},
        {0.83146961230255f, -0.55557023301960f},
        {0.70710678118655f, -0.70710678118655f}};
    float sm, cm;
    sincospif((float)tid * (-1.0f / 8192.0f), &sm, &cm);  // e^{-i*pi*tid/8192}
    float2 wm = make_float2(cm, sm);
#pragma unroll
    for (int j = 0; j < 5; ++j) {
        int k = tid + 512 * j;
        if (k > 2048) break;
        int km = (NH - k) & (NH - 1);
        float2 Zk = U[k + (k >> 4)];
        float2 Zc = U[km + (km >> 4)];
        float2 Zcc = make_float2(Zc.x, -Zc.y);
        float2 E = make_float2(0.5f * (Zk.x + Zcc.x), 0.5f * (Zk.y + Zcc.y));
        float2 Od = csub(Zk, Zcc);
        float2 O = make_float2(0.5f * Od.y, -0.5f * Od.x);  // -i/2 * Od
        float2 w = cmul(wm, EJ[j]);                          // e^{-2pi i k/16384}
        float2 X = cadd(E, cmul(w, O));
        g_xft[((size_t)b * MODES + k) * CIN + c] = make_float2(X.x * invN, X.y * invN);
    }
}

// ---------------- kernel 3: per-mode complex matmul + modulation -------------
__global__ __launch_bounds__(256) void specmul_kernel(const float* __restrict__ wr,
                                                      const float* __restrict__ wi) {
    __shared__ float  sWr[CIN * COUT];
    __shared__ float  sWi[CIN * COUT];
    __shared__ float2 sx[BB * CIN];
    __shared__ float2 stm[BB];
    const int i   = blockIdx.x;
    const int tid = threadIdx.x;

    const float* wrb = wr + (size_t)i * CIN * COUT;
    const float* wib = wi + (size_t)i * CIN * COUT;
    for (int t = tid; t < CIN * COUT; t += 256) {
        sWr[t] = wrb[t];
        sWi[t] = wib[t];
    }
    for (int t = tid; t < BB * CIN; t += 256) {
        int b = t >> 6, c = t & 63;
        sx[t] = g_xft[((size_t)b * MODES + i) * CIN + c];
    }
    if (tid < BB) stm[tid] = g_tmod[(size_t)tid * MODES + i];
    __syncthreads();

    const int o  = tid & 63;
    const int b0 = tid >> 6;     // 0..3
    float2 acc[4];
#pragma unroll
    for (int bb = 0; bb < 4; ++bb) acc[bb] = make_float2(0.f, 0.f);

#pragma unroll 4
    for (int c = 0; c < CIN; ++c) {
        float Wr = sWr[c * COUT + o];
        float Wi = sWi[c * COUT + o];
#pragma unroll
        for (int bb = 0; bb < 4; ++bb) {
            float2 xv = sx[(bb * 4 + b0) * CIN + c];
            acc[bb].x += xv.x * Wr - xv.y * Wi;
            acc[bb].y += xv.x * Wi + xv.y * Wr;
        }
    }
#pragma unroll
    for (int bb = 0; bb < 4; ++bb) {
        int b = bb * 4 + b0;
        float2 r = cmul(stm[b], acc[bb]);
        g_oft[((size_t)b * COUT + o) * MODES + i] = r;
    }
}

// ---------------- kernel 4: zero-padded irfft per (b, cout) ------------------
__global__ __launch_bounds__(512, 2) void inv_fft_kernel(float* __restrict__ out) {
    extern __shared__ float2 sh[];
    float2* U = sh;
    float2* T = sh + USIZE;
    const int tid = threadIdx.x;
    const int b = blockIdx.x >> 6;
    const int o = blockIdx.x & 63;
    const float2* of = g_oft + ((size_t)b * COUT + o) * MODES;

    build_table(T, tid);

    // Build conj(Z)[512a + m] in registers (m = tid), folding the half-complex
    // untangle: Z[k] = A + i * (e^{+2pi i k/16384} * (OF - OC)),
    // A = OF + OC, OF = out_ft[k] (k<=2048, Im(OF[0])=0), OC = conj(out_ft[N-k]).
    const float2 EA[16] = {
        { 1.00000000000000f, 0.00000000000000f},
        { 0.98078528040323f, 0.19509032201613f},
        { 0.92387953251129f, 0.38268343236509f},
        { 0.83146961230255f, 0.55557023301960f},
        { 0.70710678118655f, 0.70710678118655f},
        { 0.55557023301960f, 0.83146961230255f},
        { 0.38268343236509f, 0.92387953251129f},
        { 0.19509032201613f, 0.98078528040323f},
        { 0.00000000000000f, 1.00000000000000f},
        {-0.19509032201613f, 0.98078528040323f},
        {-0.38268343236509f, 0.92387953251129f},
        {-0.55557023301960f, 0.83146961230255f},
        {-0.70710678118655f, 0.70710678118655f},
        {-0.83146961230255f, 0.55557023301960f},
        {-0.92387953251129f, 0.38268343236509f},
        {-0.98078528040323f, 0.19509032201613f}};
    float sm, cm;
    sincospif((float)tid * (1.0f / 8192.0f), &sm, &cm);    // e^{+i*pi*tid/8192}
    float2 wm = make_float2(cm, sm);

    float2 v[16];
#pragma unroll
    for (int a = 0; a < 16; ++a) {
        int k = 512 * a + tid;
        float2 OF = make_float2(0.f, 0.f);
        float2 OC = make_float2(0.f, 0.f);
        if (k < MODES) OF = of[k];
        if (k == 0) OF.y = 0.f;                 // irfft drops Im of bin 0
        if (k >= NH - 2048) {                   // N-k <= 2048 (k>0)
            float2 t = of[NH - k];
            OC = make_float2(t.x, -t.y);
        }
        float2 A  = cadd(OF, OC);
        float2 Bd = csub(OF, OC);
        float2 w  = cmul(wm, EA[a]);            // e^{+2pi i k/16384}
        float2 Bt = cmul(w, Bd);
        v[a] = make_float2(A.x - Bt.y, -(A.y + Bt.x));   // conj(Z[k])
    }
    __syncthreads();

    fft8192_core(v, U, T, tid, false);

    // thread holds F[n] = conj(z[n]) for n = k1 + 16 q1 + 256 h + 512 p
    const int k1 = tid >> 5, q1 = (tid >> 1) & 15, h = tid & 1;
    const int nb = k1 + 16 * q1 + 256 * h;
    float* ob = out + (size_t)b * NGRID * COUT + o;
#pragma unroll
    for (int p = 0; p < 16; ++p) {
        int n = nb + 512 * p;
        float2 F = v[SLOT(p)];
        ob[(size_t)(2 * n) * COUT]     = F.x;
        ob[(size_t)(2 * n + 1) * COUT] = -F.y;
    }
}

// ---------------- launch ------------------------------------------------------
extern "C" void kernel_launch(void* const* d_in, const int* in_sizes, int n_in,
                              void* d_out, int out_size) {
    const float* x   = (const float*)d_in[0];
    const float* te  = (const float*)d_in[1];
    const float* wr  = (const float*)d_in[2];
    const float* wi  = (const float*)d_in[3];
    const float* drw = (const float*)d_in[4];
    const float* diw = (const float*)d_in[5];
    float* out = (float*)d_out;

    const int smem = (USIZE + TSIZE) * sizeof(float2);   // 102656 bytes
    cudaFuncSetAttribute(fwd_fft_kernel, cudaFuncAttributeMaxDynamicSharedMemorySize, smem);
    cudaFuncSetAttribute(inv_fft_kernel, cudaFuncAttributeMaxDynamicSharedMemorySize, smem);

    {
        int total = BB * MODES;
        int threads = 256;
        int blocks = (total + threads - 1) / threads;
        tmod_kernel<<<blocks, threads>>>(te, drw, diw);
    }
    fwd_fft_kernel<<<BB * CIN, 512, smem>>>(x);
    specmul_kernel<<<MODES, 256>>>(wr, wi);
    inv_fft_kernel<<<BB * COUT, 512, smem>>>(out);
}

// round 5
// speedup vs baseline: 2.5589x; 1.8776x over previous
#include <cuda_runtime.h>
#include <cstdint>

#define NGRID 16384
#define NH    8192
#define MODES 2049
#define BB    16
#define CIN   64
#define COUT  64
#define TDIM  256

#define ROW   546              // padded row stride (float2) for the 16 k1-rows
#define USIZE (16 * ROW)       // 8736 float2
#define TSIZE 4096             // twiddle table entries

// ---------------- scratch (static device globals; no allocation) -------------
__device__ float2 g_xft[(size_t)BB * MODES * CIN];   // (B, M, Cin)
__device__ float2 g_oft[(size_t)BB * COUT * MODES];  // (B, Cout, M)
__device__ float2 g_tmod[(size_t)BB * MODES];        // (B, M)
__device__ float2 g_twid[TSIZE];                     // W_8192^t
__device__ float  g_xT [(size_t)BB * CIN  * NGRID];  // x transposed (B, C, N)
__device__ float  g_outT[(size_t)BB * COUT * NGRID]; // out transposed (B, C, N)

// ---------------- complex helpers -------------------------------------------
__device__ __forceinline__ float2 cmul(float2 a, float2 b) {
    return make_float2(a.x * b.x - a.y * b.y, a.x * b.y + a.y * b.x);
}
__device__ __forceinline__ float2 cadd(float2 a, float2 b) { return make_float2(a.x + b.x, a.y + b.y); }
__device__ __forceinline__ float2 csub(float2 a, float2 b) { return make_float2(a.x - b.x, a.y - b.y); }

// ---------------- register DFT-4 / DFT-16 ------------------------------------
__device__ __forceinline__ void dft4(float2& a, float2& b, float2& c, float2& d) {
    float2 t0 = cadd(a, c), t1 = csub(a, c), t2 = cadd(b, d), t3 = csub(b, d);
    a = cadd(t0, t2);
    c = csub(t0, t2);
    b = cadd(t1, make_float2(t3.y, -t3.x));   // t1 - i*t3
    d = cadd(t1, make_float2(-t3.y, t3.x));   // t1 + i*t3
}

// In: v[j] natural order. Out: X[k1 + 4*k2] stored in slot (4*k1 + k2).
#define SLOT(k) ((((k) & 3) << 2) | ((k) >> 2))
__device__ __forceinline__ void dft16(float2 v[16]) {
    const float C1 = 0.9238795325112867f, S1 = 0.3826834323650898f, R = 0.7071067811865476f;
#pragma unroll
    for (int j2 = 0; j2 < 4; ++j2)
        dft4(v[j2], v[4 + j2], v[8 + j2], v[12 + j2]);
    v[5]  = cmul(v[5],  make_float2( C1, -S1));   // W16^1
    v[6]  = cmul(v[6],  make_float2( R,  -R ));   // W16^2
    v[7]  = cmul(v[7],  make_float2( S1, -C1));   // W16^3
    v[9]  = cmul(v[9],  make_float2( R,  -R ));   // W16^2
    v[10] = make_float2(v[10].y, -v[10].x);       // W16^4 = -i
    v[11] = cmul(v[11], make_float2(-R,  -R ));   // W16^6
    v[13] = cmul(v[13], make_float2( S1, -C1));   // W16^3
    v[14] = cmul(v[14], make_float2(-R,  -R ));   // W16^6
    v[15] = cmul(v[15], make_float2(-C1,  S1));   // W16^9
#pragma unroll
    for (int k1 = 0; k1 < 4; ++k1)
        dft4(v[4 * k1], v[4 * k1 + 1], v[4 * k1 + 2], v[4 * k1 + 3]);
}

// ---------------- shared 8192-pt forward-DFT core ----------------------------
// On entry: v[a] = z[512*a + m] (natural), m = tid. T[t] = W_8192^t, t<4096.
// On exit:  v[SLOT(p)] = X[k1 + 16*q1 + 256*h + 512*p] for this thread's
//           (k1 = tid>>5, q1 = (tid>>1)&15, h = tid&1).
// If store_back: also stores X[k] to U[k + (k>>4)] and syncs.
__device__ __forceinline__ void fft8192_core(float2 v[16], float2* U,
                                             const float2* T, int tid,
                                             bool store_back) {
    const int m = tid;
    // ---- stage 1: DFT16 over a, twiddle W^{m*k}, store rows U[k*ROW + m]
    dft16(v);
    {
        float2 w = T[m];                 // W^m  (m < 512)
        float2 vw = make_float2(1.f, 0.f);
#pragma unroll
        for (int k = 0; k < 16; ++k) {
            U[k * ROW + m] = cmul(v[SLOT(k)], vw);
            vw = cmul(vw, w);
        }
    }
    __syncthreads();
    // ---- stage 2: per (k1,u): DFT16 over b, twiddle W_512^{u*q1}
    {
        const int k1 = tid >> 5, u = tid & 31;
        float2* Urow = U + k1 * ROW;
#pragma unroll
        for (int b = 0; b < 16; ++b) v[b] = Urow[32 * b + u];
        dft16(v);
        float2 w = T[16 * u];            // W_512^u
        float2 vw = make_float2(1.f, 0.f);
#pragma unroll
        for (int q1 = 0; q1 < 16; ++q1) {
            Urow[34 * q1 + u] = cmul(v[SLOT(q1)], vw);
            vw = cmul(vw, w);
        }
    }
    __syncthreads();
    // ---- stage 3: per (k1,q1,h): radix-2 combine + DFT16 over u'
    {
        const int k1 = tid >> 5, q1 = (tid >> 1) & 15, h = tid & 1;
        const float2* Urow = U + k1 * ROW + 34 * q1;
#pragma unroll
        for (int up = 0; up < 16; ++up) {
            float2 ca = Urow[up];
            float2 cb = Urow[up + 16];
            if (h == 0) v[up] = cadd(ca, cb);
            else        v[up] = cmul(csub(ca, cb), T[256 * up]);   // * W_32^{u'}
        }
        __syncthreads();                 // everyone done reading U
        dft16(v);
        if (store_back) {
            const int kb = k1 + 16 * q1 + 256 * h;
#pragma unroll
            for (int p = 0; p < 16; ++p) {
                int k = kb + 512 * p;
                U[k + (k >> 4)] = v[SLOT(p)];
            }
            __syncthreads();
        }
    }
}

__device__ __forceinline__ void load_table(float2* T, int tid) {
#pragma unroll
    for (int j = 0; j < TSIZE / 512; ++j) {
        int t = tid + 512 * j;
        T[t] = g_twid[t];
    }
}

// ---------------- kernel 0: twiddle table init -------------------------------
__global__ void twid_kernel() {
    int t = blockIdx.x * blockDim.x + threadIdx.x;
    if (t >= TSIZE) return;
    float s, c;
    sincospif((float)t * (-1.0f / 4096.0f), &s, &c);   // W_8192^t
    g_twid[t] = make_float2(c, s);
}

// ---------------- kernel 1: t_mod = t_emb @ dense^T (complex) ----------------
__global__ void tmod_kernel(const float* __restrict__ te,
                            const float* __restrict__ dr,
                            const float* __restrict__ di) {
    int idx = blockIdx.x * blockDim.x + threadIdx.x;
    if (idx >= BB * MODES) return;
    int b = idx & (BB - 1);
    int i = idx >> 4;
    const float* t  = te + b * TDIM;
    const float* rr = dr + (size_t)i * TDIM;
    const float* ri = di + (size_t)i * TDIM;
    float ar = 0.f, ai = 0.f;
#pragma unroll 8
    for (int k = 0; k < TDIM; ++k) {
        float tv = t[k];
        ar += tv * rr[k];
        ai += tv * ri[k];
    }
    g_tmod[(size_t)b * MODES + i] = make_float2(ar, ai);
}

// ---------------- transpose kernels ------------------------------------------
// x (B, N, C) -> g_xT (B, C, N).  Tile 64(n) x 64(c), fully coalesced.
__global__ __launch_bounds__(256) void transpose_in_kernel(const float* __restrict__ src) {
    __shared__ float tile[64][65];
    const int tx = threadIdx.x & 63, ty = threadIdx.x >> 6;
    const int b = blockIdx.y;
    const size_t n0 = (size_t)blockIdx.x * 64;
    const float* s = src + ((size_t)b * NGRID + n0) * CIN;
#pragma unroll
    for (int i = 0; i < 16; ++i) {
        int r = ty + 4 * i;
        tile[r][tx] = s[(size_t)r * CIN + tx];
    }
    __syncthreads();
    float* d = g_xT + (size_t)b * CIN * NGRID + n0;
#pragma unroll
    for (int i = 0; i < 16; ++i) {
        int c = ty + 4 * i;
        d[(size_t)c * NGRID + tx] = tile[tx][c];
    }
}

// g_outT (B, C, N) -> out (B, N, C).
__global__ __launch_bounds__(256) void transpose_out_kernel(float* __restrict__ dst) {
    __shared__ float tile[64][65];
    const int tx = threadIdx.x & 63, ty = threadIdx.x >> 6;
    const int b = blockIdx.y;
    const size_t n0 = (size_t)blockIdx.x * 64;
    const float* s = g_outT + (size_t)b * COUT * NGRID + n0;
#pragma unroll
    for (int i = 0; i < 16; ++i) {
        int c = ty + 4 * i;
        tile[c][tx] = s[(size_t)c * NGRID + tx];
    }
    __syncthreads();
    float* d = dst + ((size_t)b * NGRID + n0) * COUT;
#pragma unroll
    for (int i = 0; i < 16; ++i) {
        int r = ty + 4 * i;
        d[(size_t)r * COUT + tx] = tile[tx][r];
    }
}

// ---------------- kernel 2: forward rfft per (b, cin) ------------------------
__global__ __launch_bounds__(512, 2) void fwd_fft_kernel() {
    extern __shared__ float2 sh[];
    float2* U = sh;
    float2* T = sh + USIZE;
    const int tid = threadIdx.x;
    const int b = blockIdx.x >> 6;
    const int c = blockIdx.x & 63;
    const float2* xb = (const float2*)(g_xT + ((size_t)b * CIN + c) * NGRID);

    // load z[512a + m] = x[2m'] + i x[2m'+1], coalesced float2
    float2 v[16];
#pragma unroll
    for (int a = 0; a < 16; ++a) v[a] = xb[512 * a + tid];
    load_table(T, tid);
    __syncthreads();

    fft8192_core(v, U, T, tid, true);

    // real-FFT untangle, forward norm (1/N)
    const float invN = 1.0f / 16384.0f;
    const float2 EJ[5] = {
        {1.f, 0.f},
        {0.98078528040323f, -0.19509032201613f},
        {0.92387953251129f, -0.38268343236509f},
        {0.83146961230255f, -0.55557023301960f},
        {0.70710678118655f, -0.70710678118655f}};
    float sm, cm;
    sincospif((float)tid * (-1.0f / 8192.0f), &sm, &cm);  // e^{-i*pi*tid/8192}
    float2 wm = make_float2(cm, sm);
#pragma unroll
    for (int j = 0; j < 5; ++j) {
        int k = tid + 512 * j;
        if (k > 2048) break;
        int km = (NH - k) & (NH - 1);
        float2 Zk = U[k + (k >> 4)];
        float2 Zc = U[km + (km >> 4)];
        float2 Zcc = make_float2(Zc.x, -Zc.y);
        float2 E = make_float2(0.5f * (Zk.x + Zcc.x), 0.5f * (Zk.y + Zcc.y));
        float2 Od = csub(Zk, Zcc);
        float2 O = make_float2(0.5f * Od.y, -0.5f * Od.x);  // -i/2 * Od
        float2 w = cmul(wm, EJ[j]);                          // e^{-2pi i k/16384}
        float2 X = cadd(E, cmul(w, O));
        g_xft[((size_t)b * MODES + k) * CIN + c] = make_float2(X.x * invN, X.y * invN);
    }
}

// ---------------- kernel 3: per-mode complex matmul + modulation -------------
__global__ __launch_bounds__(256) void specmul_kernel(const float* __restrict__ wr,
                                                      const float* __restrict__ wi) {
    __shared__ float  sWr[CIN * COUT];
    __shared__ float  sWi[CIN * COUT];
    __shared__ float2 sx[BB * CIN];
    __shared__ float2 stm[BB];
    const int i   = blockIdx.x;
    const int tid = threadIdx.x;

    const float4* wrb = (const float4*)(wr + (size_t)i * CIN * COUT);
    const float4* wib = (const float4*)(wi + (size_t)i * CIN * COUT);
#pragma unroll
    for (int t = 0; t < 4; ++t) {
        ((float4*)sWr)[tid + 256 * t] = wrb[tid + 256 * t];
        ((float4*)sWi)[tid + 256 * t] = wib[tid + 256 * t];
    }
    for (int t = tid; t < BB * CIN; t += 256) {
        int b = t >> 6, c = t & 63;
        sx[t] = g_xft[((size_t)b * MODES + i) * CIN + c];
    }
    if (tid < BB) stm[tid] = g_tmod[(size_t)tid * MODES + i];
    __syncthreads();

    const int o  = tid & 63;
    const int b0 = tid >> 6;     // 0..3
    float2 acc[4];
#pragma unroll
    for (int bb = 0; bb < 4; ++bb) acc[bb] = make_float2(0.f, 0.f);

#pragma unroll 4
    for (int c = 0; c < CIN; ++c) {
        float Wr = sWr[c * COUT + o];
        float Wi = sWi[c * COUT + o];
#pragma unroll
        for (int bb = 0; bb < 4; ++bb) {
            float2 xv = sx[(bb * 4 + b0) * CIN + c];
            acc[bb].x += xv.x * Wr - xv.y * Wi;
            acc[bb].y += xv.x * Wi + xv.y * Wr;
        }
    }
#pragma unroll
    for (int bb = 0; bb < 4; ++bb) {
        int b = bb * 4 + b0;
        float2 r = cmul(stm[b], acc[bb]);
        g_oft[((size_t)b * COUT + o) * MODES + i] = r;
    }
}

// ---------------- kernel 4: zero-padded irfft per (b, cout) ------------------
__global__ __launch_bounds__(512, 2) void inv_fft_kernel() {
    extern __shared__ float2 sh[];
    float2* U = sh;
    float2* T = sh + USIZE;
    const int tid = threadIdx.x;
    const int b = blockIdx.x >> 6;
    const int o = blockIdx.x & 63;
    const float2* of = g_oft + ((size_t)b * COUT + o) * MODES;

    load_table(T, tid);

    // Build conj(Z)[512a + m] in registers (m = tid), folding the half-complex
    // untangle: Z[k] = A + i * (e^{+2pi i k/16384} * (OF - OC)),
    // A = OF + OC, OF = out_ft[k] (k<=2048, Im(OF[0])=0), OC = conj(out_ft[N-k]).
    const float2 EA[16] = {
        { 1.00000000000000f, 0.00000000000000f},
        { 0.98078528040323f, 0.19509032201613f},
        { 0.92387953251129f, 0.38268343236509f},
        { 0.83146961230255f, 0.55557023301960f},
        { 0.70710678118655f, 0.70710678118655f},
        { 0.55557023301960f, 0.83146961230255f},
        { 0.38268343236509f, 0.92387953251129f},
        { 0.19509032201613f, 0.98078528040323f},
        { 0.00000000000000f, 1.00000000000000f},
        {-0.19509032201613f, 0.98078528040323f},
        {-0.38268343236509f, 0.92387953251129f},
        {-0.55557023301960f, 0.83146961230255f},
        {-0.70710678118655f, 0.70710678118655f},
        {-0.83146961230255f, 0.55557023301960f},
        {-0.92387953251129f, 0.38268343236509f},
        {-0.98078528040323f, 0.19509032201613f}};
    float sm, cm;
    sincospif((float)tid * (1.0f / 8192.0f), &sm, &cm);    // e^{+i*pi*tid/8192}
    float2 wm = make_float2(cm, sm);

    float2 v[16];
#pragma unroll
    for (int a = 0; a < 16; ++a) {
        int k = 512 * a + tid;
        float2 OF = make_float2(0.f, 0.f);
        float2 OC = make_float2(0.f, 0.f);
        if (k < MODES) OF = of[k];
        if (k == 0) OF.y = 0.f;                 // irfft drops Im of bin 0
        if (k >= NH - 2048) {                   // N-k <= 2048 (k>0)
            float2 t = of[NH - k];
            OC = make_float2(t.x, -t.y);
        }
        float2 A  = cadd(OF, OC);
        float2 Bd = csub(OF, OC);
        float2 w  = cmul(wm, EA[a]);            // e^{+2pi i k/16384}
        float2 Bt = cmul(w, Bd);
        v[a] = make_float2(A.x - Bt.y, -(A.y + Bt.x));   // conj(Z[k])
    }
    __syncthreads();

    fft8192_core(v, U, T, tid, true);          // F[n] now in U (skewed, natural)

    // coalesced store: out[2n], out[2n+1] are contiguous in outT row
    float2* ob = (float2*)(g_outT + ((size_t)b * COUT + o) * NGRID);
#pragma unroll
    for (int j = 0; j < 16; ++j) {
        int n = tid + 512 * j;
        float2 F = U[n + (n >> 4)];
        ob[n] = make_float2(F.x, -F.y);
    }
}

// ---------------- launch ------------------------------------------------------
extern "C" void kernel_launch(void* const* d_in, const int* in_sizes, int n_in,
                              void* d_out, int out_size) {
    const float* x   = (const float*)d_in[0];
    const float* te  = (const float*)d_in[1];
    const float* wr  = (const float*)d_in[2];
    const float* wi  = (const float*)d_in[3];
    const float* drw = (const float*)d_in[4];
    const float* diw = (const float*)d_in[5];
    float* out = (float*)d_out;

    const int smem = (USIZE + TSIZE) * sizeof(float2);   // 102656 bytes
    cudaFuncSetAttribute(fwd_fft_kernel, cudaFuncAttributeMaxDynamicSharedMemorySize, smem);
    cudaFuncSetAttribute(inv_fft_kernel, cudaFuncAttributeMaxDynamicSharedMemorySize, smem);

    twid_kernel<<<TSIZE / 512, 512>>>();
    {
        int total = BB * MODES;
        int threads = 256;
        int blocks = (total + threads - 1) / threads;
        tmod_kernel<<<blocks, threads>>>(te, drw, diw);
    }
    transpose_in_kernel<<<dim3(NGRID / 64, BB), 256>>>(x);
    fwd_fft_kernel<<<BB * CIN, 512, smem>>>();
    specmul_kernel<<<MODES, 256>>>(wr, wi);
    inv_fft_kernel<<<BB * COUT, 512, smem>>>();
    transpose_out_kernel<<<dim3(NGRID / 64, BB), 256>>>(out);
}